// round 9
// baseline (speedup 1.0000x reference)
#include <cuda_runtime.h>
#include <math.h>

#define D        128
#define NRBF     20
#define MAX_ATOMS 40960
#define CHUNK    128   // pairs staged per block iteration (32 per warp, 2 warps/pair)

// Scratch (alloc-free: __device__ globals)
__device__ __align__(16) float g_h[MAX_ATOMS * D];      // 20.5 MB
__device__ __align__(16) float g_agg[MAX_ATOMS * D];    // 20.5 MB
__device__ __align__(16) float g_WT[2][D * D];          // transposed W_in / W_out

typedef unsigned long long ull;

__device__ __forceinline__ ull pack2(float a, float b) {
    ull r; asm("mov.b64 %0, {%1,%2};" : "=l"(r) : "f"(a), "f"(b)); return r;
}
__device__ __forceinline__ float2 unpack2(ull v) {
    float2 f; asm("mov.b64 {%0,%1}, %2;" : "=f"(f.x), "=f"(f.y) : "l"(v)); return f;
}
__device__ __forceinline__ ull ffma2(ull a, ull b, ull c) {
    ull d; asm("fma.rn.f32x2 %0, %1, %2, %3;" : "=l"(d) : "l"(a), "l"(b), "l"(c)); return d;
}

__device__ __forceinline__ float ssp(float x) {
    // softplus(x) - ln2, fast+stable: max(x,0) + log(1+exp(-|x|)) - ln2
    float e = __expf(-fabsf(x));
    return fmaxf(x, 0.0f) + __logf(1.0f + e) - 0.69314718056f;
}

// Transpose W_in / W_out ([c][k] -> [k][c]) for coalesced conflict-free GEMM tiles.
__global__ void prep_kernel(const float* __restrict__ Win, const float* __restrict__ Wout) {
    int t = blockIdx.x * blockDim.x + threadIdx.x;
    if (t < D * D) {
        int c = t >> 7, k = t & 127;
        g_WT[0][k * D + c] = Win[t];
        g_WT[1][k * D + c] = Wout[t];
    }
}

__global__ void zero_kernel(int n4) {
    int t = blockIdx.x * blockDim.x + threadIdx.x;
    if (t < n4) reinterpret_cast<float4*>(g_agg)[t] = make_float4(0.f, 0.f, 0.f, 0.f);
}

// ===== GEMM: exact R5 version (known good) =====
template <int MODE>
__global__ void __launch_bounds__(256) gemm_kernel(const float* __restrict__ Xparam,
                                                   const float* __restrict__ bias,
                                                   float* __restrict__ Yparam,
                                                   int n_rows) {
    __shared__ __align__(16) float sW[32 * D];   // 16 KB [k][c] tile
    __shared__ __align__(16) float sX[64 * 32];  // 8 KB  [row][k] tile

    const float* __restrict__ X  = (MODE == 0) ? Xparam : g_agg;
    float* __restrict__ Y        = (MODE == 0) ? g_h    : Yparam;
    const float* __restrict__ Wt = g_WT[MODE];

    int r0 = blockIdx.x * 64;
    if (r0 >= n_rows) return;
    int lane = threadIdx.x & 31;
    int warp = threadIdx.x >> 5;

    ull acc[8][2];
    #pragma unroll
    for (int r = 0; r < 8; r++) { acc[r][0] = 0ull; acc[r][1] = 0ull; }

    #pragma unroll
    for (int tile = 0; tile < 4; tile++) {
        __syncthreads();
        for (int t = threadIdx.x; t < 32 * D; t += 256)
            sW[t] = Wt[tile * 32 * D + t];
        for (int t = threadIdx.x; t < 512; t += 256) {   // 512 float4 = 64 rows x 32 k
            int row = t >> 3, c4 = t & 7;
            int r = r0 + row;
            float4 v = make_float4(0.f, 0.f, 0.f, 0.f);
            if (r < n_rows)
                v = *reinterpret_cast<const float4*>(X + (size_t)r * D + tile * 32 + c4 * 4);
            reinterpret_cast<float4*>(sX)[t] = v;
        }
        __syncthreads();

        #pragma unroll
        for (int k = 0; k < 32; k++) {
            ulonglong2 w = *reinterpret_cast<const ulonglong2*>(sW + k * D + 4 * lane);
            #pragma unroll
            for (int r = 0; r < 8; r++) {
                float xv = sX[(warp * 8 + r) * 32 + k];   // broadcast
                ull x2 = pack2(xv, xv);
                acc[r][0] = ffma2(w.x, x2, acc[r][0]);
                acc[r][1] = ffma2(w.y, x2, acc[r][1]);
            }
        }
    }

    float4 b4 = *reinterpret_cast<const float4*>(bias + 4 * lane);
    #pragma unroll
    for (int r = 0; r < 8; r++) {
        int row = r0 + warp * 8 + r;
        if (row < n_rows) {
            float2 p0 = unpack2(acc[r][0]);
            float2 p1 = unpack2(acc[r][1]);
            float4 o;
            o.x = p0.x + b4.x; o.y = p0.y + b4.y;
            o.z = p1.x + b4.z; o.w = p1.y + b4.w;
            if (MODE == 1) { o.x = ssp(o.x); o.y = ssp(o.y); o.z = ssp(o.z); o.w = ssp(o.w); }
            *reinterpret_cast<float4*>(Y + (size_t)row * D + 4 * lane) = o;
        }
    }
}

// ===== Fused pair kernel v5: occupancy-first =====
//  - 2 warps per pair: warps 0-3 own channels [0,64), warps 4-7 own [64,128)
//  - lane owns 2 channels -> W_f registers = 20 packed ull (40 regs, not 80)
//  - launch_bounds(256,3): 24 warps/SM (was 16)
//  - f_ij staged duplicated (f,f) via VECTORIZED float4->ulonglong2 staging;
//    inner loop: 10x LDS.128 broadcast, zero pack MOVs
//  - gather LDG.64, scatter red.global.add.v2.f32
__global__ void __launch_bounds__(256, 3) pair_kernel(const float* __restrict__ f_ij,
                                                      const int* __restrict__ idx_i,
                                                      const int* __restrict__ idx_j,
                                                      const float* __restrict__ rcut,
                                                      const float* __restrict__ W_f,
                                                      const float* __restrict__ b_f,
                                                      int n_pairs) {
    __shared__ __align__(16) ull sFd[CHUNK * NRBF];  // 20 KB duplicated filter inputs
    __shared__ int   sI[CHUNK];
    __shared__ int   sJ[CHUNK];
    __shared__ float sR[CHUNK];

    int lane = threadIdx.x & 31;
    int warp = threadIdx.x >> 5;
    int half = warp >> 2;          // channel half: 0 or 1
    int sub  = warp & 3;           // pair subrange within chunk
    int c0   = half * 64 + 2 * lane;   // first of this lane's 2 channels

    // ---- This lane's 2 weight rows, packed (one-time): 20 ull = 40 regs ----
    ull wp[NRBF];
    {
        const float4* r0p = reinterpret_cast<const float4*>(W_f + (size_t)c0 * NRBF);
        const float4* r1p = reinterpret_cast<const float4*>(W_f + (size_t)(c0 + 1) * NRBF);
        #pragma unroll
        for (int v = 0; v < 5; v++) {
            float4 a = r0p[v], b = r1p[v];
            wp[4*v+0] = pack2(a.x, b.x);
            wp[4*v+1] = pack2(a.y, b.y);
            wp[4*v+2] = pack2(a.z, b.z);
            wp[4*v+3] = pack2(a.w, b.w);
        }
    }
    const ull bias2 = pack2(b_f[c0], b_f[c0 + 1]);

    for (int base = blockIdx.x * CHUNK; base < n_pairs; base += gridDim.x * CHUNK) {
        int cnt = min(CHUNK, n_pairs - base);
        __syncthreads();
        // Vectorized duplicated staging: float4 load -> 2x ulonglong2 store
        if (cnt == CHUNK) {
            const float4* src = reinterpret_cast<const float4*>(f_ij + (size_t)base * NRBF);
            for (int t = threadIdx.x; t < CHUNK * NRBF / 4; t += 256) {
                float4 v = src[t];
                ulonglong2* dst = reinterpret_cast<ulonglong2*>(&sFd[t * 4]);
                dst[0] = make_ulonglong2(pack2(v.x, v.x), pack2(v.y, v.y));
                dst[1] = make_ulonglong2(pack2(v.z, v.z), pack2(v.w, v.w));
            }
        } else {
            for (int t = threadIdx.x; t < cnt * NRBF; t += 256) {
                float v = f_ij[(size_t)base * NRBF + t];
                sFd[t] = pack2(v, v);
            }
        }
        for (int t = threadIdx.x; t < cnt; t += 256) {
            sI[t] = idx_i[base + t];
            sJ[t] = idx_j[base + t];
            sR[t] = rcut[base + t];
        }
        __syncthreads();

        int q0 = sub * 32;
        int qend = min(q0 + 32, cnt);
        for (int q = q0; q < qend; q++) {
            const ull* f = sFd + q * NRBF;
            int i = sI[q], j = sJ[q];
            float rc = sR[q];

            // prefetch neighbor features (2 floats for this lane's channels)
            const float2 h2 = *reinterpret_cast<const float2*>(
                g_h + (size_t)j * D + c0);

            ull acc = bias2;
            #pragma unroll
            for (int k2 = 0; k2 < NRBF / 2; k2++) {
                ulonglong2 ff = *reinterpret_cast<const ulonglong2*>(f + 2 * k2);
                acc = ffma2(wp[2 * k2],     ff.x, acc);
                acc = ffma2(wp[2 * k2 + 1], ff.y, acc);
            }
            float2 p = unpack2(acc);
            float s0 = ssp(p.x) * rc;
            float s1 = ssp(p.y) * rc;

            float vx = h2.x * s0, vy = h2.y * s1;
            float* dst = g_agg + (size_t)i * D + c0;
            asm volatile("red.global.add.v2.f32 [%0], {%1,%2};"
                         :: "l"(dst), "f"(vx), "f"(vy)
                         : "memory");
        }
    }
}

extern "C" void kernel_launch(void* const* d_in, const int* in_sizes, int n_in,
                              void* d_out, int out_size) {
    const float* x     = (const float*)d_in[0];
    const float* f_ij  = (const float*)d_in[1];
    const int*   idx_i = (const int*)  d_in[2];
    const int*   idx_j = (const int*)  d_in[3];
    const float* rcut  = (const float*)d_in[4];
    const float* W_in  = (const float*)d_in[5];
    const float* b_in  = (const float*)d_in[6];
    const float* W_f   = (const float*)d_in[7];
    const float* b_f   = (const float*)d_in[8];
    const float* W_out = (const float*)d_in[9];
    const float* b_out = (const float*)d_in[10];
    float* out = (float*)d_out;
    (void)n_in; (void)out_size;

    int n_atoms = in_sizes[0] / D;
    int n_pairs = in_sizes[2];

    prep_kernel<<<(D * D + 255) / 256, 256>>>(W_in, W_out);
    int n4 = (n_atoms * D) / 4;
    zero_kernel<<<(n4 + 255) / 256, 256>>>(n4);

    int gblocks = (n_atoms + 63) / 64;
    gemm_kernel<0><<<gblocks, 256>>>(x, b_in, nullptr, n_atoms);

    pair_kernel<<<1184, 256>>>(f_ij, idx_i, idx_j, rcut, W_f, b_f, n_pairs);

    gemm_kernel<1><<<gblocks, 256>>>(nullptr, b_out, out, n_atoms);
}

// round 11
// speedup vs baseline: 1.1319x; 1.1319x over previous
#include <cuda_runtime.h>
#include <cstdint>
#include <math.h>

#define D        128
#define NRBF     20
#define MAX_ATOMS 40960
#define CHUNK    128   // pairs staged per block iteration (16 per warp)
#define LOG2E    1.4426950408889634f
#define LN2      0.69314718055994531f

// Scratch (alloc-free: __device__ globals)
__device__ __align__(16) float g_h[MAX_ATOMS * D];      // 20.5 MB
__device__ __align__(16) float g_agg[MAX_ATOMS * D];    // 20.5 MB
__device__ __align__(16) float g_WT[2][D * D];          // transposed W_in / W_out

typedef unsigned long long ull;

__device__ __forceinline__ ull pack2(float a, float b) {
    ull r; asm("mov.b64 %0, {%1,%2};" : "=l"(r) : "f"(a), "f"(b)); return r;
}
__device__ __forceinline__ float2 unpack2(ull v) {
    float2 f; asm("mov.b64 {%0,%1}, %2;" : "=f"(f.x), "=f"(f.y) : "l"(v)); return f;
}
__device__ __forceinline__ ull ffma2(ull a, ull b, ull c) {
    ull d; asm("fma.rn.f32x2 %0, %1, %2, %3;" : "=l"(d) : "l"(a), "l"(b), "l"(c)); return d;
}
__device__ __forceinline__ float ex2(float x) {
    float r; asm("ex2.approx.f32 %0, %1;" : "=f"(r) : "f"(x)); return r;
}
__device__ __forceinline__ float lg2(float x) {
    float r; asm("lg2.approx.f32 %0, %1;" : "=f"(r) : "f"(x)); return r;
}

__device__ __forceinline__ float ssp(float x) {
    // softplus(x) - ln2, fast+stable (used only in the small output GEMM)
    float e = __expf(-fabsf(x));
    return fmaxf(x, 0.0f) + __logf(1.0f + e) - LN2;
}

// 16-byte cp.async with src-size zero-fill (tail-safe)
__device__ __forceinline__ void cp_async16(void* smem_dst, const void* gsrc, int src_bytes) {
    unsigned int s = (unsigned int)__cvta_generic_to_shared(smem_dst);
    asm volatile("cp.async.ca.shared.global [%0], [%1], 16, %2;"
                 :: "r"(s), "l"(gsrc), "r"(src_bytes));
}
#define CP_COMMIT() asm volatile("cp.async.commit_group;")
#define CP_WAIT1()  asm volatile("cp.async.wait_group 1;")

// Transpose W_in / W_out ([c][k] -> [k][c]) for coalesced conflict-free GEMM tiles.
__global__ void prep_kernel(const float* __restrict__ Win, const float* __restrict__ Wout) {
    int t = blockIdx.x * blockDim.x + threadIdx.x;
    if (t < D * D) {
        int c = t >> 7, k = t & 127;
        g_WT[0][k * D + c] = Win[t];
        g_WT[1][k * D + c] = Wout[t];
    }
}

__global__ void zero_kernel(int n4) {
    int t = blockIdx.x * blockDim.x + threadIdx.x;
    if (t < n4) reinterpret_cast<float4*>(g_agg)[t] = make_float4(0.f, 0.f, 0.f, 0.f);
}

// ===== GEMM: exact R5 version (known good) =====
template <int MODE>
__global__ void __launch_bounds__(256) gemm_kernel(const float* __restrict__ Xparam,
                                                   const float* __restrict__ bias,
                                                   float* __restrict__ Yparam,
                                                   int n_rows) {
    __shared__ __align__(16) float sW[32 * D];   // 16 KB [k][c] tile
    __shared__ __align__(16) float sX[64 * 32];  // 8 KB  [row][k] tile

    const float* __restrict__ X  = (MODE == 0) ? Xparam : g_agg;
    float* __restrict__ Y        = (MODE == 0) ? g_h    : Yparam;
    const float* __restrict__ Wt = g_WT[MODE];

    int r0 = blockIdx.x * 64;
    if (r0 >= n_rows) return;
    int lane = threadIdx.x & 31;
    int warp = threadIdx.x >> 5;

    ull acc[8][2];
    #pragma unroll
    for (int r = 0; r < 8; r++) { acc[r][0] = 0ull; acc[r][1] = 0ull; }

    #pragma unroll
    for (int tile = 0; tile < 4; tile++) {
        __syncthreads();
        for (int t = threadIdx.x; t < 32 * D; t += 256)
            sW[t] = Wt[tile * 32 * D + t];
        for (int t = threadIdx.x; t < 512; t += 256) {   // 512 float4 = 64 rows x 32 k
            int row = t >> 3, c4 = t & 7;
            int r = r0 + row;
            float4 v = make_float4(0.f, 0.f, 0.f, 0.f);
            if (r < n_rows)
                v = *reinterpret_cast<const float4*>(X + (size_t)r * D + tile * 32 + c4 * 4);
            reinterpret_cast<float4*>(sX)[t] = v;
        }
        __syncthreads();

        #pragma unroll
        for (int k = 0; k < 32; k++) {
            ulonglong2 w = *reinterpret_cast<const ulonglong2*>(sW + k * D + 4 * lane);
            #pragma unroll
            for (int r = 0; r < 8; r++) {
                float xv = sX[(warp * 8 + r) * 32 + k];   // broadcast
                ull x2 = pack2(xv, xv);
                acc[r][0] = ffma2(w.x, x2, acc[r][0]);
                acc[r][1] = ffma2(w.y, x2, acc[r][1]);
            }
        }
    }

    float4 b4 = *reinterpret_cast<const float4*>(bias + 4 * lane);
    #pragma unroll
    for (int r = 0; r < 8; r++) {
        int row = r0 + warp * 8 + r;
        if (row < n_rows) {
            float2 p0 = unpack2(acc[r][0]);
            float2 p1 = unpack2(acc[r][1]);
            float4 o;
            o.x = p0.x + b4.x; o.y = p0.y + b4.y;
            o.z = p1.x + b4.z; o.w = p1.y + b4.w;
            if (MODE == 1) { o.x = ssp(o.x); o.y = ssp(o.y); o.z = ssp(o.z); o.w = ssp(o.w); }
            *reinterpret_cast<float4*>(Y + (size_t)row * D + 4 * lane) = o;
        }
    }
}

// ===== Fused pair kernel v6 =====
//  - 1 warp/pair, lane owns 4 channels (R5 shape, proven best)
//  - weights pre-scaled by log2e, packed as (w[2k],w[2k+1]) per channel:
//    ffma2 consumes RAW adjacent f pairs -> 5 LDS.128/pair, no duplication,
//    no pack MOVs; one horizontal add per channel at the end
//  - ssp computed in log2 domain: 2 MUFU + 4 ALU/FMA per channel
//  - f/idx/rcut staged via DOUBLE-BUFFERED cp.async (staging overlaps compute)
//  - gather h[idx_j] (L2-resident), scatter red.global.add.v4.f32
__global__ void __launch_bounds__(256, 2) pair_kernel(const float* __restrict__ f_ij,
                                                      const int* __restrict__ idx_i,
                                                      const int* __restrict__ idx_j,
                                                      const float* __restrict__ rcut,
                                                      const float* __restrict__ W_f,
                                                      const float* __restrict__ b_f,
                                                      int n_pairs) {
    __shared__ __align__(16) float sF[2][CHUNK * NRBF];  // 2 x 10 KB raw f
    __shared__ __align__(16) int   sI[2][CHUNK];
    __shared__ __align__(16) int   sJ[2][CHUNK];
    __shared__ __align__(16) float sR[2][CHUNK];

    int lane = threadIdx.x & 31;
    int warp = threadIdx.x >> 5;
    int tid  = threadIdx.x;

    // ---- This lane's 4 weight rows, pre-scaled by LOG2E, packed (w2k, w2k+1) ----
    ull wp[4][NRBF / 2];
    #pragma unroll
    for (int r = 0; r < 4; r++) {
        const float4* rp = reinterpret_cast<const float4*>(W_f + (size_t)(4 * lane + r) * NRBF);
        #pragma unroll
        for (int v = 0; v < 5; v++) {
            float4 a = rp[v];
            wp[r][2 * v]     = pack2(a.x * LOG2E, a.y * LOG2E);
            wp[r][2 * v + 1] = pack2(a.z * LOG2E, a.w * LOG2E);
        }
    }
    // bias (log2 domain) in the even-k partial slot
    float4 bf4 = *reinterpret_cast<const float4*>(b_f + 4 * lane);
    const ull pb0 = pack2(bf4.x * LOG2E, 0.f);
    const ull pb1 = pack2(bf4.y * LOG2E, 0.f);
    const ull pb2 = pack2(bf4.z * LOG2E, 0.f);
    const ull pb3 = pack2(bf4.w * LOG2E, 0.f);

    const int stride = gridDim.x * CHUNK;
    int base0 = blockIdx.x * CHUNK;
    if (base0 >= n_pairs) return;

    auto stage = [&](int buf, int bs) {
        int cnt = min(CHUNK, n_pairs - bs);
        int bytes_f = cnt * NRBF * 4;
        const char* gf = reinterpret_cast<const char*>(f_ij + (size_t)bs * NRBF);
        char* df = reinterpret_cast<char*>(sF[buf]);
        for (int t = tid; t < CHUNK * NRBF / 4; t += 256) {   // 640 16B lines
            int off = t * 16;
            int sz = bytes_f - off; sz = sz < 0 ? 0 : (sz > 16 ? 16 : sz);
            cp_async16(df + off, gf + off, sz);
        }
        int bytes_i = cnt * 4;
        if (tid < 96) {
            int a = tid >> 5, t = tid & 31;
            int off = t * 16;
            int sz = bytes_i - off; sz = sz < 0 ? 0 : (sz > 16 ? 16 : sz);
            if (a == 0) cp_async16(reinterpret_cast<char*>(sI[buf]) + off,
                                   reinterpret_cast<const char*>(idx_i + bs) + off, sz);
            else if (a == 1) cp_async16(reinterpret_cast<char*>(sJ[buf]) + off,
                                        reinterpret_cast<const char*>(idx_j + bs) + off, sz);
            else cp_async16(reinterpret_cast<char*>(sR[buf]) + off,
                            reinterpret_cast<const char*>(rcut + bs) + off, sz);
        }
    };

    stage(0, base0);
    CP_COMMIT();

    int buf = 0;
    for (int base = base0; base < n_pairs; base += stride) {
        int nxt = base + stride;
        if (nxt < n_pairs) stage(buf ^ 1, nxt);
        CP_COMMIT();
        CP_WAIT1();          // current buf's group complete
        __syncthreads();

        int cnt = min(CHUNK, n_pairs - base);
        int q0 = warp * 16;
        int qend = min(q0 + 16, cnt);

        for (int q = q0; q < qend; q++) {
            int j = sJ[buf][q];
            // gather early: covered by the FFMA/ssp chain below
            const float4 h4 = *reinterpret_cast<const float4*>(
                g_h + (size_t)j * D + 4 * lane);
            int i = sI[buf][q];
            float rc = sR[buf][q];
            const ulonglong2* f2p = reinterpret_cast<const ulonglong2*>(sF[buf] + q * NRBF);

            ull p0 = pb0, p1 = pb1, p2 = pb2, p3 = pb3;
            #pragma unroll
            for (int v = 0; v < 5; v++) {                 // 5x LDS.128 broadcast
                ulonglong2 ff = f2p[v];                   // (f[4v],f[4v+1]),(f[4v+2],f[4v+3])
                p0 = ffma2(wp[0][2 * v],     ff.x, p0);
                p1 = ffma2(wp[1][2 * v],     ff.x, p1);
                p2 = ffma2(wp[2][2 * v],     ff.x, p2);
                p3 = ffma2(wp[3][2 * v],     ff.x, p3);
                p0 = ffma2(wp[0][2 * v + 1], ff.y, p0);
                p1 = ffma2(wp[1][2 * v + 1], ff.y, p1);
                p2 = ffma2(wp[2][2 * v + 1], ff.y, p2);
                p3 = ffma2(wp[3][2 * v + 1], ff.y, p3);
            }
            float2 u0 = unpack2(p0), u1 = unpack2(p1), u2 = unpack2(p2), u3 = unpack2(p3);
            float t0 = u0.x + u0.y;   // log2-domain preactivation per channel
            float t1 = u1.x + u1.y;
            float t2 = u2.x + u2.y;
            float t3 = u3.x + u3.y;

            float lr = LN2 * rc, nlr = -lr;
            // ssp(x)*rc = lr*(max(t,0)+lg2(1+2^-|t|)) - lr
            float s0 = fmaf(fmaxf(t0, 0.f) + lg2(1.0f + ex2(-fabsf(t0))), lr, nlr);
            float s1 = fmaf(fmaxf(t1, 0.f) + lg2(1.0f + ex2(-fabsf(t1))), lr, nlr);
            float s2 = fmaf(fmaxf(t2, 0.f) + lg2(1.0f + ex2(-fabsf(t2))), lr, nlr);
            float s3 = fmaf(fmaxf(t3, 0.f) + lg2(1.0f + ex2(-fabsf(t3))), lr, nlr);

            float vx = h4.x * s0, vy = h4.y * s1, vz = h4.z * s2, vw = h4.w * s3;
            float* dst = g_agg + (size_t)i * D + 4 * lane;
            asm volatile("red.global.add.v4.f32 [%0], {%1,%2,%3,%4};"
                         :: "l"(dst), "f"(vx), "f"(vy), "f"(vz), "f"(vw)
                         : "memory");
        }
        __syncthreads();     // all reads of buf done before it is refilled
        buf ^= 1;
    }
}

extern "C" void kernel_launch(void* const* d_in, const int* in_sizes, int n_in,
                              void* d_out, int out_size) {
    const float* x     = (const float*)d_in[0];
    const float* f_ij  = (const float*)d_in[1];
    const int*   idx_i = (const int*)  d_in[2];
    const int*   idx_j = (const int*)  d_in[3];
    const float* rcut  = (const float*)d_in[4];
    const float* W_in  = (const float*)d_in[5];
    const float* b_in  = (const float*)d_in[6];
    const float* W_f   = (const float*)d_in[7];
    const float* b_f   = (const float*)d_in[8];
    const float* W_out = (const float*)d_in[9];
    const float* b_out = (const float*)d_in[10];
    float* out = (float*)d_out;
    (void)n_in; (void)out_size;

    int n_atoms = in_sizes[0] / D;
    int n_pairs = in_sizes[2];

    prep_kernel<<<(D * D + 255) / 256, 256>>>(W_in, W_out);
    int n4 = (n_atoms * D) / 4;
    zero_kernel<<<(n4 + 255) / 256, 256>>>(n4);

    int gblocks = (n_atoms + 63) / 64;
    gemm_kernel<0><<<gblocks, 256>>>(x, b_in, nullptr, n_atoms);

    pair_kernel<<<1184, 256>>>(f_ij, idx_i, idx_j, rcut, W_f, b_f, n_pairs);

    gemm_kernel<1><<<gblocks, 256>>>(nullptr, b_out, out, n_atoms);
}

// round 12
// speedup vs baseline: 1.1331x; 1.0010x over previous
#include <cuda_runtime.h>
#include <cstdint>
#include <math.h>

#define D        128
#define NRBF     20
#define MAX_ATOMS 40960
#define CHUNK    128   // pairs staged per block iteration (16 per warp)
#define LOG2E    1.4426950408889634f
#define LN2      0.69314718055994531f

// Scratch (alloc-free: __device__ globals)
__device__ __align__(16) float g_h[MAX_ATOMS * D];      // 20.5 MB
__device__ __align__(16) float g_agg[MAX_ATOMS * D];    // 20.5 MB
__device__ __align__(16) float g_WT[2][D * D];          // transposed W_in / W_out

typedef unsigned long long ull;

__device__ __forceinline__ ull pack2(float a, float b) {
    ull r; asm("mov.b64 %0, {%1,%2};" : "=l"(r) : "f"(a), "f"(b)); return r;
}
__device__ __forceinline__ float2 unpack2(ull v) {
    float2 f; asm("mov.b64 {%0,%1}, %2;" : "=f"(f.x), "=f"(f.y) : "l"(v)); return f;
}
__device__ __forceinline__ ull ffma2(ull a, ull b, ull c) {
    ull d; asm("fma.rn.f32x2 %0, %1, %2, %3;" : "=l"(d) : "l"(a), "l"(b), "l"(c)); return d;
}
__device__ __forceinline__ float ex2(float x) {
    float r; asm("ex2.approx.f32 %0, %1;" : "=f"(r) : "f"(x)); return r;
}
__device__ __forceinline__ float lg2(float x) {
    float r; asm("lg2.approx.f32 %0, %1;" : "=f"(r) : "f"(x)); return r;
}

__device__ __forceinline__ float ssp(float x) {
    // softplus(x) - ln2, fast+stable (used only in the small output GEMM)
    float e = __expf(-fabsf(x));
    return fmaxf(x, 0.0f) + __logf(1.0f + e) - LN2;
}

// 16-byte cp.async with src-size zero-fill (tail-safe)
__device__ __forceinline__ void cp_async16(void* smem_dst, const void* gsrc, int src_bytes) {
    unsigned int s = (unsigned int)__cvta_generic_to_shared(smem_dst);
    asm volatile("cp.async.ca.shared.global [%0], [%1], 16, %2;"
                 :: "r"(s), "l"(gsrc), "r"(src_bytes));
}
#define CP_COMMIT() asm volatile("cp.async.commit_group;")
#define CP_WAIT1()  asm volatile("cp.async.wait_group 1;")

// Transpose W_in / W_out ([c][k] -> [k][c]) for coalesced conflict-free GEMM tiles.
__global__ void prep_kernel(const float* __restrict__ Win, const float* __restrict__ Wout) {
    int t = blockIdx.x * blockDim.x + threadIdx.x;
    if (t < D * D) {
        int c = t >> 7, k = t & 127;
        g_WT[0][k * D + c] = Win[t];
        g_WT[1][k * D + c] = Wout[t];
    }
}

__global__ void zero_kernel(int n4) {
    int t = blockIdx.x * blockDim.x + threadIdx.x;
    if (t < n4) reinterpret_cast<float4*>(g_agg)[t] = make_float4(0.f, 0.f, 0.f, 0.f);
}

// ===== GEMM: exact R5 version (known good) =====
template <int MODE>
__global__ void __launch_bounds__(256) gemm_kernel(const float* __restrict__ Xparam,
                                                   const float* __restrict__ bias,
                                                   float* __restrict__ Yparam,
                                                   int n_rows) {
    __shared__ __align__(16) float sW[32 * D];   // 16 KB [k][c] tile
    __shared__ __align__(16) float sX[64 * 32];  // 8 KB  [row][k] tile

    const float* __restrict__ X  = (MODE == 0) ? Xparam : g_agg;
    float* __restrict__ Y        = (MODE == 0) ? g_h    : Yparam;
    const float* __restrict__ Wt = g_WT[MODE];

    int r0 = blockIdx.x * 64;
    if (r0 >= n_rows) return;
    int lane = threadIdx.x & 31;
    int warp = threadIdx.x >> 5;

    ull acc[8][2];
    #pragma unroll
    for (int r = 0; r < 8; r++) { acc[r][0] = 0ull; acc[r][1] = 0ull; }

    #pragma unroll
    for (int tile = 0; tile < 4; tile++) {
        __syncthreads();
        for (int t = threadIdx.x; t < 32 * D; t += 256)
            sW[t] = Wt[tile * 32 * D + t];
        for (int t = threadIdx.x; t < 512; t += 256) {   // 512 float4 = 64 rows x 32 k
            int row = t >> 3, c4 = t & 7;
            int r = r0 + row;
            float4 v = make_float4(0.f, 0.f, 0.f, 0.f);
            if (r < n_rows)
                v = *reinterpret_cast<const float4*>(X + (size_t)r * D + tile * 32 + c4 * 4);
            reinterpret_cast<float4*>(sX)[t] = v;
        }
        __syncthreads();

        #pragma unroll
        for (int k = 0; k < 32; k++) {
            ulonglong2 w = *reinterpret_cast<const ulonglong2*>(sW + k * D + 4 * lane);
            #pragma unroll
            for (int r = 0; r < 8; r++) {
                float xv = sX[(warp * 8 + r) * 32 + k];   // broadcast
                ull x2 = pack2(xv, xv);
                acc[r][0] = ffma2(w.x, x2, acc[r][0]);
                acc[r][1] = ffma2(w.y, x2, acc[r][1]);
            }
        }
    }

    float4 b4 = *reinterpret_cast<const float4*>(bias + 4 * lane);
    #pragma unroll
    for (int r = 0; r < 8; r++) {
        int row = r0 + warp * 8 + r;
        if (row < n_rows) {
            float2 p0 = unpack2(acc[r][0]);
            float2 p1 = unpack2(acc[r][1]);
            float4 o;
            o.x = p0.x + b4.x; o.y = p0.y + b4.y;
            o.z = p1.x + b4.z; o.w = p1.y + b4.w;
            if (MODE == 1) { o.x = ssp(o.x); o.y = ssp(o.y); o.z = ssp(o.z); o.w = ssp(o.w); }
            *reinterpret_cast<float4*>(Y + (size_t)row * D + 4 * lane) = o;
        }
    }
}

// ===== Fused pair kernel v6 =====
//  - 1 warp/pair, lane owns 4 channels (R5 shape, proven best)
//  - weights pre-scaled by log2e, packed as (w[2k],w[2k+1]) per channel:
//    ffma2 consumes RAW adjacent f pairs -> 5 LDS.128/pair, no duplication,
//    no pack MOVs; one horizontal add per channel at the end
//  - ssp computed in log2 domain: 2 MUFU + 4 ALU/FMA per channel
//  - f/idx/rcut staged via DOUBLE-BUFFERED cp.async (staging overlaps compute)
//  - gather h[idx_j] (L2-resident), scatter red.global.add.v4.f32
__global__ void __launch_bounds__(256, 2) pair_kernel(const float* __restrict__ f_ij,
                                                      const int* __restrict__ idx_i,
                                                      const int* __restrict__ idx_j,
                                                      const float* __restrict__ rcut,
                                                      const float* __restrict__ W_f,
                                                      const float* __restrict__ b_f,
                                                      int n_pairs) {
    __shared__ __align__(16) float sF[2][CHUNK * NRBF];  // 2 x 10 KB raw f
    __shared__ __align__(16) int   sI[2][CHUNK];
    __shared__ __align__(16) int   sJ[2][CHUNK];
    __shared__ __align__(16) float sR[2][CHUNK];

    int lane = threadIdx.x & 31;
    int warp = threadIdx.x >> 5;
    int tid  = threadIdx.x;

    // ---- This lane's 4 weight rows, pre-scaled by LOG2E, packed (w2k, w2k+1) ----
    ull wp[4][NRBF / 2];
    #pragma unroll
    for (int r = 0; r < 4; r++) {
        const float4* rp = reinterpret_cast<const float4*>(W_f + (size_t)(4 * lane + r) * NRBF);
        #pragma unroll
        for (int v = 0; v < 5; v++) {
            float4 a = rp[v];
            wp[r][2 * v]     = pack2(a.x * LOG2E, a.y * LOG2E);
            wp[r][2 * v + 1] = pack2(a.z * LOG2E, a.w * LOG2E);
        }
    }
    // bias (log2 domain) in the even-k partial slot
    float4 bf4 = *reinterpret_cast<const float4*>(b_f + 4 * lane);
    const ull pb0 = pack2(bf4.x * LOG2E, 0.f);
    const ull pb1 = pack2(bf4.y * LOG2E, 0.f);
    const ull pb2 = pack2(bf4.z * LOG2E, 0.f);
    const ull pb3 = pack2(bf4.w * LOG2E, 0.f);

    const int stride = gridDim.x * CHUNK;
    int base0 = blockIdx.x * CHUNK;
    if (base0 >= n_pairs) return;

    auto stage = [&](int buf, int bs) {
        int cnt = min(CHUNK, n_pairs - bs);
        int bytes_f = cnt * NRBF * 4;
        const char* gf = reinterpret_cast<const char*>(f_ij + (size_t)bs * NRBF);
        char* df = reinterpret_cast<char*>(sF[buf]);
        for (int t = tid; t < CHUNK * NRBF / 4; t += 256) {   // 640 16B lines
            int off = t * 16;
            int sz = bytes_f - off; sz = sz < 0 ? 0 : (sz > 16 ? 16 : sz);
            cp_async16(df + off, gf + off, sz);
        }
        int bytes_i = cnt * 4;
        if (tid < 96) {
            int a = tid >> 5, t = tid & 31;
            int off = t * 16;
            int sz = bytes_i - off; sz = sz < 0 ? 0 : (sz > 16 ? 16 : sz);
            if (a == 0) cp_async16(reinterpret_cast<char*>(sI[buf]) + off,
                                   reinterpret_cast<const char*>(idx_i + bs) + off, sz);
            else if (a == 1) cp_async16(reinterpret_cast<char*>(sJ[buf]) + off,
                                        reinterpret_cast<const char*>(idx_j + bs) + off, sz);
            else cp_async16(reinterpret_cast<char*>(sR[buf]) + off,
                            reinterpret_cast<const char*>(rcut + bs) + off, sz);
        }
    };

    stage(0, base0);
    CP_COMMIT();

    int buf = 0;
    for (int base = base0; base < n_pairs; base += stride) {
        int nxt = base + stride;
        if (nxt < n_pairs) stage(buf ^ 1, nxt);
        CP_COMMIT();
        CP_WAIT1();          // current buf's group complete
        __syncthreads();

        int cnt = min(CHUNK, n_pairs - base);
        int q0 = warp * 16;
        int qend = min(q0 + 16, cnt);

        for (int q = q0; q < qend; q++) {
            int j = sJ[buf][q];
            // gather early: covered by the FFMA/ssp chain below
            const float4 h4 = *reinterpret_cast<const float4*>(
                g_h + (size_t)j * D + 4 * lane);
            int i = sI[buf][q];
            float rc = sR[buf][q];
            const ulonglong2* f2p = reinterpret_cast<const ulonglong2*>(sF[buf] + q * NRBF);

            ull p0 = pb0, p1 = pb1, p2 = pb2, p3 = pb3;
            #pragma unroll
            for (int v = 0; v < 5; v++) {                 // 5x LDS.128 broadcast
                ulonglong2 ff = f2p[v];                   // (f[4v],f[4v+1]),(f[4v+2],f[4v+3])
                p0 = ffma2(wp[0][2 * v],     ff.x, p0);
                p1 = ffma2(wp[1][2 * v],     ff.x, p1);
                p2 = ffma2(wp[2][2 * v],     ff.x, p2);
                p3 = ffma2(wp[3][2 * v],     ff.x, p3);
                p0 = ffma2(wp[0][2 * v + 1], ff.y, p0);
                p1 = ffma2(wp[1][2 * v + 1], ff.y, p1);
                p2 = ffma2(wp[2][2 * v + 1], ff.y, p2);
                p3 = ffma2(wp[3][2 * v + 1], ff.y, p3);
            }
            float2 u0 = unpack2(p0), u1 = unpack2(p1), u2 = unpack2(p2), u3 = unpack2(p3);
            float t0 = u0.x + u0.y;   // log2-domain preactivation per channel
            float t1 = u1.x + u1.y;
            float t2 = u2.x + u2.y;
            float t3 = u3.x + u3.y;

            float lr = LN2 * rc, nlr = -lr;
            // ssp(x)*rc = lr*(max(t,0)+lg2(1+2^-|t|)) - lr
            float s0 = fmaf(fmaxf(t0, 0.f) + lg2(1.0f + ex2(-fabsf(t0))), lr, nlr);
            float s1 = fmaf(fmaxf(t1, 0.f) + lg2(1.0f + ex2(-fabsf(t1))), lr, nlr);
            float s2 = fmaf(fmaxf(t2, 0.f) + lg2(1.0f + ex2(-fabsf(t2))), lr, nlr);
            float s3 = fmaf(fmaxf(t3, 0.f) + lg2(1.0f + ex2(-fabsf(t3))), lr, nlr);

            float vx = h4.x * s0, vy = h4.y * s1, vz = h4.z * s2, vw = h4.w * s3;
            float* dst = g_agg + (size_t)i * D + 4 * lane;
            asm volatile("red.global.add.v4.f32 [%0], {%1,%2,%3,%4};"
                         :: "l"(dst), "f"(vx), "f"(vy), "f"(vz), "f"(vw)
                         : "memory");
        }
        __syncthreads();     // all reads of buf done before it is refilled
        buf ^= 1;
    }
}

extern "C" void kernel_launch(void* const* d_in, const int* in_sizes, int n_in,
                              void* d_out, int out_size) {
    const float* x     = (const float*)d_in[0];
    const float* f_ij  = (const float*)d_in[1];
    const int*   idx_i = (const int*)  d_in[2];
    const int*   idx_j = (const int*)  d_in[3];
    const float* rcut  = (const float*)d_in[4];
    const float* W_in  = (const float*)d_in[5];
    const float* b_in  = (const float*)d_in[6];
    const float* W_f   = (const float*)d_in[7];
    const float* b_f   = (const float*)d_in[8];
    const float* W_out = (const float*)d_in[9];
    const float* b_out = (const float*)d_in[10];
    float* out = (float*)d_out;
    (void)n_in; (void)out_size;

    int n_atoms = in_sizes[0] / D;
    int n_pairs = in_sizes[2];

    prep_kernel<<<(D * D + 255) / 256, 256>>>(W_in, W_out);
    int n4 = (n_atoms * D) / 4;
    zero_kernel<<<(n4 + 255) / 256, 256>>>(n4);

    int gblocks = (n_atoms + 63) / 64;
    gemm_kernel<0><<<gblocks, 256>>>(x, b_in, nullptr, n_atoms);

    pair_kernel<<<1184, 256>>>(f_ij, idx_i, idx_j, rcut, W_f, b_f, n_pairs);

    gemm_kernel<1><<<gblocks, 256>>>(nullptr, b_out, out, n_atoms);
}

// round 13
// speedup vs baseline: 1.1353x; 1.0019x over previous
#include <cuda_runtime.h>
#include <cstdint>
#include <math.h>

#define D        128
#define NRBF     20
#define MAX_ATOMS 40960
#define CHUNK    128   // pairs staged per block iteration (16 per warp)
#define LOG2E    1.4426950408889634f
#define LN2      0.69314718055994531f

// Scratch (alloc-free: __device__ globals)
__device__ __align__(16) float g_h[MAX_ATOMS * D];      // 20.5 MB
__device__ __align__(16) float g_agg[MAX_ATOMS * D];    // 20.5 MB
__device__ __align__(16) float g_WT[2][D * D];          // transposed W_in / W_out

typedef unsigned long long ull;

__device__ __forceinline__ ull pack2(float a, float b) {
    ull r; asm("mov.b64 %0, {%1,%2};" : "=l"(r) : "f"(a), "f"(b)); return r;
}
__device__ __forceinline__ float2 unpack2(ull v) {
    float2 f; asm("mov.b64 {%0,%1}, %2;" : "=f"(f.x), "=f"(f.y) : "l"(v)); return f;
}
__device__ __forceinline__ ull ffma2(ull a, ull b, ull c) {
    ull d; asm("fma.rn.f32x2 %0, %1, %2, %3;" : "=l"(d) : "l"(a), "l"(b), "l"(c)); return d;
}
__device__ __forceinline__ float ex2(float x) {
    float r; asm("ex2.approx.f32 %0, %1;" : "=f"(r) : "f"(x)); return r;
}
__device__ __forceinline__ float lg2(float x) {
    float r; asm("lg2.approx.f32 %0, %1;" : "=f"(r) : "f"(x)); return r;
}

__device__ __forceinline__ float ssp(float x) {
    // softplus(x) - ln2, fast+stable (used only in the small output GEMM)
    float e = __expf(-fabsf(x));
    return fmaxf(x, 0.0f) + __logf(1.0f + e) - LN2;
}

// 16-byte cp.async with src-size zero-fill (tail-safe)
__device__ __forceinline__ void cp_async16(void* smem_dst, const void* gsrc, int src_bytes) {
    unsigned int s = (unsigned int)__cvta_generic_to_shared(smem_dst);
    asm volatile("cp.async.ca.shared.global [%0], [%1], 16, %2;"
                 :: "r"(s), "l"(gsrc), "r"(src_bytes));
}
#define CP_COMMIT() asm volatile("cp.async.commit_group;")
#define CP_WAIT1()  asm volatile("cp.async.wait_group 1;")

// Transpose W_in / W_out ([c][k] -> [k][c]) for coalesced conflict-free GEMM tiles.
__global__ void prep_kernel(const float* __restrict__ Win, const float* __restrict__ Wout) {
    int t = blockIdx.x * blockDim.x + threadIdx.x;
    if (t < D * D) {
        int c = t >> 7, k = t & 127;
        g_WT[0][k * D + c] = Win[t];
        g_WT[1][k * D + c] = Wout[t];
    }
}

__global__ void zero_kernel(int n4) {
    int t = blockIdx.x * blockDim.x + threadIdx.x;
    if (t < n4) reinterpret_cast<float4*>(g_agg)[t] = make_float4(0.f, 0.f, 0.f, 0.f);
}

// ===== GEMM: exact R5 version (known good) =====
template <int MODE>
__global__ void __launch_bounds__(256) gemm_kernel(const float* __restrict__ Xparam,
                                                   const float* __restrict__ bias,
                                                   float* __restrict__ Yparam,
                                                   int n_rows) {
    __shared__ __align__(16) float sW[32 * D];   // 16 KB [k][c] tile
    __shared__ __align__(16) float sX[64 * 32];  // 8 KB  [row][k] tile

    const float* __restrict__ X  = (MODE == 0) ? Xparam : g_agg;
    float* __restrict__ Y        = (MODE == 0) ? g_h    : Yparam;
    const float* __restrict__ Wt = g_WT[MODE];

    int r0 = blockIdx.x * 64;
    if (r0 >= n_rows) return;
    int lane = threadIdx.x & 31;
    int warp = threadIdx.x >> 5;

    ull acc[8][2];
    #pragma unroll
    for (int r = 0; r < 8; r++) { acc[r][0] = 0ull; acc[r][1] = 0ull; }

    #pragma unroll
    for (int tile = 0; tile < 4; tile++) {
        __syncthreads();
        for (int t = threadIdx.x; t < 32 * D; t += 256)
            sW[t] = Wt[tile * 32 * D + t];
        for (int t = threadIdx.x; t < 512; t += 256) {   // 512 float4 = 64 rows x 32 k
            int row = t >> 3, c4 = t & 7;
            int r = r0 + row;
            float4 v = make_float4(0.f, 0.f, 0.f, 0.f);
            if (r < n_rows)
                v = *reinterpret_cast<const float4*>(X + (size_t)r * D + tile * 32 + c4 * 4);
            reinterpret_cast<float4*>(sX)[t] = v;
        }
        __syncthreads();

        #pragma unroll
        for (int k = 0; k < 32; k++) {
            ulonglong2 w = *reinterpret_cast<const ulonglong2*>(sW + k * D + 4 * lane);
            #pragma unroll
            for (int r = 0; r < 8; r++) {
                float xv = sX[(warp * 8 + r) * 32 + k];   // broadcast
                ull x2 = pack2(xv, xv);
                acc[r][0] = ffma2(w.x, x2, acc[r][0]);
                acc[r][1] = ffma2(w.y, x2, acc[r][1]);
            }
        }
    }

    float4 b4 = *reinterpret_cast<const float4*>(bias + 4 * lane);
    #pragma unroll
    for (int r = 0; r < 8; r++) {
        int row = r0 + warp * 8 + r;
        if (row < n_rows) {
            float2 p0 = unpack2(acc[r][0]);
            float2 p1 = unpack2(acc[r][1]);
            float4 o;
            o.x = p0.x + b4.x; o.y = p0.y + b4.y;
            o.z = p1.x + b4.z; o.w = p1.y + b4.w;
            if (MODE == 1) { o.x = ssp(o.x); o.y = ssp(o.y); o.z = ssp(o.z); o.w = ssp(o.w); }
            *reinterpret_cast<float4*>(Y + (size_t)row * D + 4 * lane) = o;
        }
    }
}

// ===== Fused pair kernel v6 =====
//  - 1 warp/pair, lane owns 4 channels (R5 shape, proven best)
//  - weights pre-scaled by log2e, packed as (w[2k],w[2k+1]) per channel:
//    ffma2 consumes RAW adjacent f pairs -> 5 LDS.128/pair, no duplication,
//    no pack MOVs; one horizontal add per channel at the end
//  - ssp computed in log2 domain: 2 MUFU + 4 ALU/FMA per channel
//  - f/idx/rcut staged via DOUBLE-BUFFERED cp.async (staging overlaps compute)
//  - gather h[idx_j] (L2-resident), scatter red.global.add.v4.f32
__global__ void __launch_bounds__(256, 2) pair_kernel(const float* __restrict__ f_ij,
                                                      const int* __restrict__ idx_i,
                                                      const int* __restrict__ idx_j,
                                                      const float* __restrict__ rcut,
                                                      const float* __restrict__ W_f,
                                                      const float* __restrict__ b_f,
                                                      int n_pairs) {
    __shared__ __align__(16) float sF[2][CHUNK * NRBF];  // 2 x 10 KB raw f
    __shared__ __align__(16) int   sI[2][CHUNK];
    __shared__ __align__(16) int   sJ[2][CHUNK];
    __shared__ __align__(16) float sR[2][CHUNK];

    int lane = threadIdx.x & 31;
    int warp = threadIdx.x >> 5;
    int tid  = threadIdx.x;

    // ---- This lane's 4 weight rows, pre-scaled by LOG2E, packed (w2k, w2k+1) ----
    ull wp[4][NRBF / 2];
    #pragma unroll
    for (int r = 0; r < 4; r++) {
        const float4* rp = reinterpret_cast<const float4*>(W_f + (size_t)(4 * lane + r) * NRBF);
        #pragma unroll
        for (int v = 0; v < 5; v++) {
            float4 a = rp[v];
            wp[r][2 * v]     = pack2(a.x * LOG2E, a.y * LOG2E);
            wp[r][2 * v + 1] = pack2(a.z * LOG2E, a.w * LOG2E);
        }
    }
    // bias (log2 domain) in the even-k partial slot
    float4 bf4 = *reinterpret_cast<const float4*>(b_f + 4 * lane);
    const ull pb0 = pack2(bf4.x * LOG2E, 0.f);
    const ull pb1 = pack2(bf4.y * LOG2E, 0.f);
    const ull pb2 = pack2(bf4.z * LOG2E, 0.f);
    const ull pb3 = pack2(bf4.w * LOG2E, 0.f);

    const int stride = gridDim.x * CHUNK;
    int base0 = blockIdx.x * CHUNK;
    if (base0 >= n_pairs) return;

    auto stage = [&](int buf, int bs) {
        int cnt = min(CHUNK, n_pairs - bs);
        int bytes_f = cnt * NRBF * 4;
        const char* gf = reinterpret_cast<const char*>(f_ij + (size_t)bs * NRBF);
        char* df = reinterpret_cast<char*>(sF[buf]);
        for (int t = tid; t < CHUNK * NRBF / 4; t += 256) {   // 640 16B lines
            int off = t * 16;
            int sz = bytes_f - off; sz = sz < 0 ? 0 : (sz > 16 ? 16 : sz);
            cp_async16(df + off, gf + off, sz);
        }
        int bytes_i = cnt * 4;
        if (tid < 96) {
            int a = tid >> 5, t = tid & 31;
            int off = t * 16;
            int sz = bytes_i - off; sz = sz < 0 ? 0 : (sz > 16 ? 16 : sz);
            if (a == 0) cp_async16(reinterpret_cast<char*>(sI[buf]) + off,
                                   reinterpret_cast<const char*>(idx_i + bs) + off, sz);
            else if (a == 1) cp_async16(reinterpret_cast<char*>(sJ[buf]) + off,
                                        reinterpret_cast<const char*>(idx_j + bs) + off, sz);
            else cp_async16(reinterpret_cast<char*>(sR[buf]) + off,
                            reinterpret_cast<const char*>(rcut + bs) + off, sz);
        }
    };

    stage(0, base0);
    CP_COMMIT();

    int buf = 0;
    for (int base = base0; base < n_pairs; base += stride) {
        int nxt = base + stride;
        if (nxt < n_pairs) stage(buf ^ 1, nxt);
        CP_COMMIT();
        CP_WAIT1();          // current buf's group complete
        __syncthreads();

        int cnt = min(CHUNK, n_pairs - base);
        int q0 = warp * 16;
        int qend = min(q0 + 16, cnt);

        for (int q = q0; q < qend; q++) {
            int j = sJ[buf][q];
            // gather early: covered by the FFMA/ssp chain below
            const float4 h4 = *reinterpret_cast<const float4*>(
                g_h + (size_t)j * D + 4 * lane);
            int i = sI[buf][q];
            float rc = sR[buf][q];
            const ulonglong2* f2p = reinterpret_cast<const ulonglong2*>(sF[buf] + q * NRBF);

            ull p0 = pb0, p1 = pb1, p2 = pb2, p3 = pb3;
            #pragma unroll
            for (int v = 0; v < 5; v++) {                 // 5x LDS.128 broadcast
                ulonglong2 ff = f2p[v];                   // (f[4v],f[4v+1]),(f[4v+2],f[4v+3])
                p0 = ffma2(wp[0][2 * v],     ff.x, p0);
                p1 = ffma2(wp[1][2 * v],     ff.x, p1);
                p2 = ffma2(wp[2][2 * v],     ff.x, p2);
                p3 = ffma2(wp[3][2 * v],     ff.x, p3);
                p0 = ffma2(wp[0][2 * v + 1], ff.y, p0);
                p1 = ffma2(wp[1][2 * v + 1], ff.y, p1);
                p2 = ffma2(wp[2][2 * v + 1], ff.y, p2);
                p3 = ffma2(wp[3][2 * v + 1], ff.y, p3);
            }
            float2 u0 = unpack2(p0), u1 = unpack2(p1), u2 = unpack2(p2), u3 = unpack2(p3);
            float t0 = u0.x + u0.y;   // log2-domain preactivation per channel
            float t1 = u1.x + u1.y;
            float t2 = u2.x + u2.y;
            float t3 = u3.x + u3.y;

            float lr = LN2 * rc, nlr = -lr;
            // ssp(x)*rc = lr*(max(t,0)+lg2(1+2^-|t|)) - lr
            float s0 = fmaf(fmaxf(t0, 0.f) + lg2(1.0f + ex2(-fabsf(t0))), lr, nlr);
            float s1 = fmaf(fmaxf(t1, 0.f) + lg2(1.0f + ex2(-fabsf(t1))), lr, nlr);
            float s2 = fmaf(fmaxf(t2, 0.f) + lg2(1.0f + ex2(-fabsf(t2))), lr, nlr);
            float s3 = fmaf(fmaxf(t3, 0.f) + lg2(1.0f + ex2(-fabsf(t3))), lr, nlr);

            float vx = h4.x * s0, vy = h4.y * s1, vz = h4.z * s2, vw = h4.w * s3;
            float* dst = g_agg + (size_t)i * D + 4 * lane;
            asm volatile("red.global.add.v4.f32 [%0], {%1,%2,%3,%4};"
                         :: "l"(dst), "f"(vx), "f"(vy), "f"(vz), "f"(vw)
                         : "memory");
        }
        __syncthreads();     // all reads of buf done before it is refilled
        buf ^= 1;
    }
}

extern "C" void kernel_launch(void* const* d_in, const int* in_sizes, int n_in,
                              void* d_out, int out_size) {
    const float* x     = (const float*)d_in[0];
    const float* f_ij  = (const float*)d_in[1];
    const int*   idx_i = (const int*)  d_in[2];
    const int*   idx_j = (const int*)  d_in[3];
    const float* rcut  = (const float*)d_in[4];
    const float* W_in  = (const float*)d_in[5];
    const float* b_in  = (const float*)d_in[6];
    const float* W_f   = (const float*)d_in[7];
    const float* b_f   = (const float*)d_in[8];
    const float* W_out = (const float*)d_in[9];
    const float* b_out = (const float*)d_in[10];
    float* out = (float*)d_out;
    (void)n_in; (void)out_size;

    int n_atoms = in_sizes[0] / D;
    int n_pairs = in_sizes[2];

    prep_kernel<<<(D * D + 255) / 256, 256>>>(W_in, W_out);
    int n4 = (n_atoms * D) / 4;
    zero_kernel<<<(n4 + 255) / 256, 256>>>(n4);

    int gblocks = (n_atoms + 63) / 64;
    gemm_kernel<0><<<gblocks, 256>>>(x, b_in, nullptr, n_atoms);

    pair_kernel<<<1184, 256>>>(f_ij, idx_i, idx_j, rcut, W_f, b_f, n_pairs);

    gemm_kernel<1><<<gblocks, 256>>>(nullptr, b_out, out, n_atoms);
}